// round 1
// baseline (speedup 1.0000x reference)
#include <cuda_runtime.h>
#include <cuda_bf16.h>

#define B 8
#define C 256
#define HW 2304
#define DK 32
#define C2 512

// Scratch (device globals — no allocation allowed)
__device__ float g_vg[B * C];    // vg[b][c]  = (Wv @ GvT[b])[c]
__device__ float g_wqk[B * C];   // wqk[b][c] = sum_d kg[b][d] * Wq[d][c]
__device__ float g_qb[B];        // qb[b]     = bq . kg[b]

__device__ __forceinline__ float ex2f(float x) {
    float y;
    asm("ex2.approx.ftz.f32 %0, %1;" : "=f"(y) : "f"(x));
    return y;
}

// ---------------------------------------------------------------------------
// Kernel 1: text branch + rank-1 collapse coefficients. One block per batch.
// ---------------------------------------------------------------------------
__global__ __launch_bounds__(256)
void prep_kernel(const float* __restrict__ text,
                 const float* __restrict__ Wg1, const float* __restrict__ bg1,
                 const float* __restrict__ ln_g, const float* __restrict__ ln_b,
                 const float* __restrict__ Wg2, const float* __restrict__ bg2,
                 const float* __restrict__ Wq,  const float* __restrict__ bq,
                 const float* __restrict__ Wk,  const float* __restrict__ Wv)
{
    const int b = blockIdx.x;
    const int tid = threadIdx.x;   // 256 threads

    __shared__ float tf[C];
    __shared__ float t[C2];
    __shared__ float red[256];
    __shared__ float gv[C];
    __shared__ float kg[DK];

    tf[tid] = text[b * C + tid];
    __syncthreads();

    // t = text @ Wg1 + bg1   [2C]
    #pragma unroll
    for (int jj = 0; jj < 2; jj++) {
        const int j = tid + jj * 256;
        float acc = bg1[j];
        #pragma unroll 8
        for (int c = 0; c < C; c++) acc = fmaf(tf[c], Wg1[c * C2 + j], acc);
        t[j] = acc;
    }
    __syncthreads();

    // LayerNorm over 512
    red[tid] = t[tid] + t[tid + 256];
    __syncthreads();
    for (int s = 128; s > 0; s >>= 1) { if (tid < s) red[tid] += red[tid + s]; __syncthreads(); }
    const float mu = red[0] * (1.0f / C2);
    __syncthreads();
    {
        float d0 = t[tid] - mu, d1 = t[tid + 256] - mu;
        red[tid] = d0 * d0 + d1 * d1;
    }
    __syncthreads();
    for (int s = 128; s > 0; s >>= 1) { if (tid < s) red[tid] += red[tid + s]; __syncthreads(); }
    const float rstd = rsqrtf(red[0] * (1.0f / C2) + 1e-5f);
    __syncthreads();

    // affine + exact GELU
    #pragma unroll
    for (int jj = 0; jj < 2; jj++) {
        const int j = tid + jj * 256;
        float x = (t[j] - mu) * rstd * ln_g[j] + ln_b[j];
        t[j] = 0.5f * x * (1.0f + erff(x * 0.7071067811865476f));
    }
    __syncthreads();

    // GvT = t @ Wg2 + bg2  [C]
    {
        float acc = bg2[tid];
        #pragma unroll 8
        for (int j = 0; j < C2; j++) acc = fmaf(t[j], Wg2[j * C + tid], acc);
        gv[tid] = acc;
    }
    __syncthreads();

    // vg[c] = sum_c' Wv[c,c'] * gv[c']
    {
        float acc = 0.0f;
        const float* wr = Wv + tid * C;
        #pragma unroll 8
        for (int c2 = 0; c2 < C; c2++) acc = fmaf(wr[c2], gv[c2], acc);
        g_vg[b * C + tid] = acc;
    }

    // kg[d] = sum_c Wk[d,c] * gv[c]
    if (tid < DK) {
        float acc = 0.0f;
        const float* wr = Wk + tid * C;
        #pragma unroll 8
        for (int c = 0; c < C; c++) acc = fmaf(wr[c], gv[c], acc);
        kg[tid] = acc;
    }
    __syncthreads();

    // wqk[c] = sum_d kg[d] * Wq[d,c]
    {
        float acc = 0.0f;
        #pragma unroll
        for (int d = 0; d < DK; d++) acc = fmaf(kg[d], Wq[d * C + tid], acc);
        g_wqk[b * C + tid] = acc;
    }

    if (tid == 0) {
        float s = 0.0f;
        #pragma unroll
        for (int d = 0; d < DK; d++) s = fmaf(bq[d], kg[d], s);
        g_qb[b] = s;
    }
}

// ---------------------------------------------------------------------------
// Kernel 2: per-pixel collapsed attention. grid = (HW/128, B), block = 128.
// ---------------------------------------------------------------------------
__global__ __launch_bounds__(128)
void attn_kernel(const float* __restrict__ img,
                 const float* __restrict__ l,
                 const float* __restrict__ bv,
                 const float* __restrict__ gamma_p,
                 float* __restrict__ out)
{
    const int b = blockIdx.y;
    const int tid = threadIdx.x;
    const int i = blockIdx.x * 128 + tid;   // pixel index, always < HW

    __shared__ float ls[HW];
    __shared__ float wq[C];
    __shared__ float vgs[C];
    __shared__ float bvs[C];
    __shared__ float red[128];

    // load l; track local max/min
    float mx = -1e30f, mn = 1e30f;
    #pragma unroll
    for (int j = tid; j < HW; j += 128) {
        float v = l[j];
        ls[j] = v;
        mx = fmaxf(mx, v);
        mn = fminf(mn, v);
    }
    wq[tid]        = g_wqk[b * C + tid];
    wq[tid + 128]  = g_wqk[b * C + tid + 128];
    vgs[tid]       = g_vg[b * C + tid];
    vgs[tid + 128] = g_vg[b * C + tid + 128];
    bvs[tid]       = bv[tid];
    bvs[tid + 128] = bv[tid + 128];

    red[tid] = mx; __syncthreads();
    for (int s = 64; s > 0; s >>= 1) { if (tid < s) red[tid] = fmaxf(red[tid], red[tid + s]); __syncthreads(); }
    const float lmax = red[0]; __syncthreads();
    red[tid] = mn; __syncthreads();
    for (int s = 64; s > 0; s >>= 1) { if (tid < s) red[tid] = fminf(red[tid], red[tid + s]); __syncthreads(); }
    const float lmin = red[0]; __syncthreads();

    // a[b,i] = wqk[b,:] . x[b,:,i] + qb[b]
    const float* xb = img + (size_t)b * C * HW + i;
    float a = g_qb[b];
    #pragma unroll 8
    for (int c = 0; c < C; c++) a = fmaf(wq[c], xb[(size_t)c * HW], a);

    // s[b,i] = sum_j l[j] exp(a l[j]) / sum_j exp(a l[j]), stabilized, in exp2 domain
    const float al = a * 1.4426950408889634f;
    const float m2 = (al > 0.0f) ? al * lmax : al * lmin;
    float S = 0.0f, T = 0.0f;
    #pragma unroll 8
    for (int j = 0; j < HW; j++) {
        const float lj = ls[j];
        const float e = ex2f(fmaf(al, lj, -m2));
        S += e;
        T = fmaf(lj, e, T);
    }
    const float sv = T / S;
    const float gm = *gamma_p;

    // out[b,c,i] = img + gamma * (vg[c]*s + bv[c])
    const size_t base = (size_t)b * C * HW + i;
    #pragma unroll 4
    for (int c = 0; c < C; c++) {
        const size_t idx = base + (size_t)c * HW;
        out[idx] = fmaf(gm, fmaf(vgs[c], sv, bvs[c]), img[idx]);
    }
}

extern "C" void kernel_launch(void* const* d_in, const int* in_sizes, int n_in,
                              void* d_out, int out_size)
{
    const float* img   = (const float*)d_in[0];
    const float* text  = (const float*)d_in[1];
    const float* l     = (const float*)d_in[2];
    const float* Wg1   = (const float*)d_in[3];
    const float* bg1   = (const float*)d_in[4];
    const float* ln_g  = (const float*)d_in[5];
    const float* ln_b  = (const float*)d_in[6];
    const float* Wg2   = (const float*)d_in[7];
    const float* bg2   = (const float*)d_in[8];
    const float* Wq    = (const float*)d_in[9];
    const float* bq    = (const float*)d_in[10];
    const float* Wk    = (const float*)d_in[11];
    // d_in[12] = bk : cancels in softmax, unused
    const float* Wv    = (const float*)d_in[13];
    const float* bv    = (const float*)d_in[14];
    const float* gamma = (const float*)d_in[15];
    float* out = (float*)d_out;

    prep_kernel<<<B, 256>>>(text, Wg1, bg1, ln_g, ln_b, Wg2, bg2, Wq, bq, Wk, Wv);
    dim3 grid(HW / 128, B);
    attn_kernel<<<grid, 128>>>(img, l, bv, gamma, out);
}

// round 3
// speedup vs baseline: 2.8165x; 2.8165x over previous
#include <cuda_runtime.h>
#include <cuda_bf16.h>

#define B 8
#define C 256
#define HW 2304
#define DK 32
#define C2 512

// Scratch (device globals — no allocation allowed)
__device__ float g_t[B * C2];    // text branch activations
__device__ float g_gv[B * C];    // GvT
__device__ float g_kg[B * DK];   // kg = Wk @ GvT
__device__ float g_vg[B * C];    // vg = Wv @ GvT
__device__ float g_wqk[B * C];   // wqk = kg @ Wq
__device__ float g_qb[B];        // qb = bq . kg

__device__ __forceinline__ float ex2f(float x) {
    float y;
    asm("ex2.approx.ftz.f32 %0, %1;" : "=f"(y) : "f"(x));
    return y;
}

__device__ __forceinline__ float warp_sum(float v) {
    #pragma unroll
    for (int o = 16; o; o >>= 1) v += __shfl_xor_sync(0xffffffffu, v, o);
    return v;
}

// ---------------------------------------------------------------------------
// P1: t = text @ Wg1 + bg1.  4096 outputs, one warp each. grid 512 x 256.
// ---------------------------------------------------------------------------
__global__ __launch_bounds__(256)
void p1_kernel(const float* __restrict__ text,
               const float* __restrict__ Wg1, const float* __restrict__ bg1)
{
    const int warp = (blockIdx.x * 256 + threadIdx.x) >> 5;  // 0..4095
    const int lane = threadIdx.x & 31;
    const int b = warp >> 9;
    const int j = warp & 511;
    const float* tx = text + b * C;
    float acc = 0.0f;
    #pragma unroll
    for (int t = 0; t < 8; t++) {
        const int c = lane + 32 * t;
        acc = fmaf(tx[c], Wg1[c * C2 + j], acc);
    }
    acc = warp_sum(acc);
    if (lane == 0) g_t[b * C2 + j] = acc + bg1[j];
}

// ---------------------------------------------------------------------------
// P2: LayerNorm + exact GELU, per batch. grid 8 x 512.
// ---------------------------------------------------------------------------
__global__ __launch_bounds__(512)
void p2_kernel(const float* __restrict__ ln_g, const float* __restrict__ ln_b)
{
    const int b = blockIdx.x;
    const int tid = threadIdx.x;
    const int lane = tid & 31, wid = tid >> 5;   // 16 warps
    __shared__ float red[16];
    __shared__ float bcast[2];

    const float v = g_t[b * C2 + tid];

    float s = warp_sum(v);
    if (lane == 0) red[wid] = s;
    __syncthreads();
    if (wid == 0) {
        float r = (lane < 16) ? red[lane] : 0.0f;
        r = warp_sum(r);
        if (lane == 0) bcast[0] = r * (1.0f / C2);
    }
    __syncthreads();
    const float mu = bcast[0];

    const float d = v - mu;
    float s2 = warp_sum(d * d);
    if (lane == 0) red[wid] = s2;
    __syncthreads();
    if (wid == 0) {
        float r = (lane < 16) ? red[lane] : 0.0f;
        r = warp_sum(r);
        if (lane == 0) bcast[1] = rsqrtf(r * (1.0f / C2) + 1e-5f);
    }
    __syncthreads();
    const float rstd = bcast[1];

    float x = d * rstd * ln_g[tid] + ln_b[tid];
    g_t[b * C2 + tid] = 0.5f * x * (1.0f + erff(x * 0.7071067811865476f));
}

// ---------------------------------------------------------------------------
// P3: GvT = t @ Wg2 + bg2.  2048 outputs, one warp each. grid 256 x 256.
// ---------------------------------------------------------------------------
__global__ __launch_bounds__(256)
void p3_kernel(const float* __restrict__ Wg2, const float* __restrict__ bg2)
{
    const int warp = (blockIdx.x * 256 + threadIdx.x) >> 5;  // 0..2047
    const int lane = threadIdx.x & 31;
    const int b = warp >> 8;
    const int c = warp & 255;
    float acc = 0.0f;
    #pragma unroll
    for (int t = 0; t < 16; t++) {
        const int k = lane + 32 * t;
        acc = fmaf(g_t[b * C2 + k], Wg2[k * C + c], acc);
    }
    acc = warp_sum(acc);
    if (lane == 0) g_gv[b * C + c] = acc + bg2[c];
}

// ---------------------------------------------------------------------------
// P4: vg = Wv @ GvT (2048 warps) and kg = Wk @ GvT (256 warps). grid 288 x 256.
// ---------------------------------------------------------------------------
__global__ __launch_bounds__(256)
void p4_kernel(const float* __restrict__ Wv, const float* __restrict__ Wk)
{
    const int warp = (blockIdx.x * 256 + threadIdx.x) >> 5;  // 0..2303
    const int lane = threadIdx.x & 31;
    if (warp < 2048) {
        const int b = warp >> 8;
        const int c = warp & 255;
        const float* gv = g_gv + b * C;
        const float* wr = Wv + c * C;
        float acc = 0.0f;
        #pragma unroll
        for (int t = 0; t < 8; t++) {
            const int k = lane + 32 * t;
            acc = fmaf(gv[k], wr[k], acc);
        }
        acc = warp_sum(acc);
        if (lane == 0) g_vg[b * C + c] = acc;
    } else {
        const int w2 = warp - 2048;
        const int b = w2 >> 5;
        const int d = w2 & 31;
        const float* gv = g_gv + b * C;
        const float* wr = Wk + d * C;
        float acc = 0.0f;
        #pragma unroll
        for (int t = 0; t < 8; t++) {
            const int k = lane + 32 * t;
            acc = fmaf(gv[k], wr[k], acc);
        }
        acc = warp_sum(acc);
        if (lane == 0) g_kg[b * DK + d] = acc;
    }
}

// ---------------------------------------------------------------------------
// P5: wqk = kg @ Wq, qb = bq . kg. grid 8 x 256.
// ---------------------------------------------------------------------------
__global__ __launch_bounds__(256)
void p5_kernel(const float* __restrict__ Wq, const float* __restrict__ bq)
{
    const int b = blockIdx.x;
    const int tid = threadIdx.x;
    __shared__ float kg[DK];
    if (tid < DK) kg[tid] = g_kg[b * DK + tid];
    __syncthreads();
    float acc = 0.0f;
    #pragma unroll
    for (int d = 0; d < DK; d++) acc = fmaf(kg[d], Wq[d * C + tid], acc);
    g_wqk[b * C + tid] = acc;
    if (tid == 0) {
        float s = 0.0f;
        #pragma unroll
        for (int d = 0; d < DK; d++) s = fmaf(bq[d], kg[d], s);
        g_qb[b] = s;
    }
}

// ---------------------------------------------------------------------------
// Attention: block = 256 threads, 64 pixels, 4 threads per pixel
// (both the C-dot and the HW exp-sum are 4-way split). grid (36, 8).
// ---------------------------------------------------------------------------
__global__ __launch_bounds__(256)
void attn_kernel(const float* __restrict__ img,
                 const float* __restrict__ l,
                 const float* __restrict__ bv,
                 const float* __restrict__ gamma_p,
                 float* __restrict__ out)
{
    const int b = blockIdx.y;
    const int tid = threadIdx.x;
    const int s = tid >> 6;      // 0..3  split index
    const int p = tid & 63;      // pixel within block
    const int i = blockIdx.x * 64 + p;
    const int lane = tid & 31, wid = tid >> 5;

    __shared__ float ls[HW];
    __shared__ float wq[C];
    __shared__ float vgs[C];
    __shared__ float bvs[C];
    __shared__ float partA[256];
    __shared__ float partS[256];
    __shared__ float partT[256];
    __shared__ float sval[64];
    __shared__ float rmx[8], rmn[8];

    const float gm = *gamma_p;   // hoisted: LDG overlaps everything below

    // load l (+min/max), coefficient vectors
    float mx = -1e30f, mn = 1e30f;
    #pragma unroll
    for (int j = tid; j < HW; j += 256) {
        const float v = l[j];
        ls[j] = v;
        mx = fmaxf(mx, v);
        mn = fminf(mn, v);
    }
    wq[tid]  = g_wqk[b * C + tid];
    vgs[tid] = g_vg[b * C + tid];
    bvs[tid] = bv[tid];

    #pragma unroll
    for (int o = 16; o; o >>= 1) {
        mx = fmaxf(mx, __shfl_xor_sync(0xffffffffu, mx, o));
        mn = fminf(mn, __shfl_xor_sync(0xffffffffu, mn, o));
    }
    if (lane == 0) { rmx[wid] = mx; rmn[wid] = mn; }
    __syncthreads();
    float lmax = rmx[0], lmin = rmn[0];
    #pragma unroll
    for (int k = 1; k < 8; k++) {
        lmax = fmaxf(lmax, rmx[k]);
        lmin = fminf(lmin, rmn[k]);
    }

    // a[b,i] = wqk . x[:,i]  (4-way c split: c = s + 4t)
    const float* xb = img + (size_t)b * C * HW + i;
    float a = 0.0f;
    #pragma unroll 16
    for (int t = 0; t < 64; t++) {
        const int c = s + 4 * t;
        a = fmaf(wq[c], xb[(size_t)c * HW], a);
    }
    partA[tid] = a;
    __syncthreads();
    float af = g_qb[b] + partA[p] + partA[64 + p] + partA[128 + p] + partA[192 + p];

    // softmax-weighted sum of l, rank-1 logits; exp2 domain, 4-way j split
    const float al = af * 1.4426950408889634f;
    const float m2 = (al > 0.0f) ? al * lmax : al * lmin;
    float S = 0.0f, T = 0.0f;
    #pragma unroll 8
    for (int j = s; j < HW; j += 4) {
        const float lj = ls[j];
        const float e = ex2f(fmaf(al, lj, -m2));
        S += e;
        T = fmaf(lj, e, T);
    }
    partS[tid] = S;
    partT[tid] = T;
    __syncthreads();
    if (s == 0) {
        const float Ss = partS[p] + partS[64 + p] + partS[128 + p] + partS[192 + p];
        const float Ts = partT[p] + partT[64 + p] + partT[128 + p] + partT[192 + p];
        sval[p] = Ts / Ss;
    }
    __syncthreads();

    // out[b,c,i] = img + gamma * (vg[c]*sv + bv[c]); thread covers c = s*64..s*64+63
    const float sv = sval[p];
    const size_t base = (size_t)b * C * HW + i;
    #pragma unroll 8
    for (int cc = 0; cc < 64; cc++) {
        const int c = s * 64 + cc;
        const size_t idx = base + (size_t)c * HW;
        out[idx] = fmaf(gm, fmaf(vgs[c], sv, bvs[c]), img[idx]);
    }
}

extern "C" void kernel_launch(void* const* d_in, const int* in_sizes, int n_in,
                              void* d_out, int out_size)
{
    const float* img   = (const float*)d_in[0];
    const float* text  = (const float*)d_in[1];
    const float* l     = (const float*)d_in[2];
    const float* Wg1   = (const float*)d_in[3];
    const float* bg1   = (const float*)d_in[4];
    const float* ln_g  = (const float*)d_in[5];
    const float* ln_b  = (const float*)d_in[6];
    const float* Wg2   = (const float*)d_in[7];
    const float* bg2   = (const float*)d_in[8];
    const float* Wq    = (const float*)d_in[9];
    const float* bq    = (const float*)d_in[10];
    const float* Wk    = (const float*)d_in[11];
    // d_in[12] = bk : cancels in softmax, unused
    const float* Wv    = (const float*)d_in[13];
    const float* bv    = (const float*)d_in[14];
    const float* gamma = (const float*)d_in[15];
    float* out = (float*)d_out;

    p1_kernel<<<512, 256>>>(text, Wg1, bg1);
    p2_kernel<<<8, 512>>>(ln_g, ln_b);
    p3_kernel<<<256, 256>>>(Wg2, bg2);
    p4_kernel<<<288, 256>>>(Wv, Wk);
    p5_kernel<<<8, 256>>>(Wq, bq);
    dim3 grid(HW / 64, B);
    attn_kernel<<<grid, 256>>>(img, l, bv, gamma, out);
}

// round 4
// speedup vs baseline: 3.1319x; 1.1120x over previous
#include <cuda_runtime.h>
#include <cuda_bf16.h>

#define B 8
#define C 256
#define HW 2304
#define DK 32
#define C2 512

// Scratch (device globals — no allocation allowed)
__device__ float g_t[B * C2];    // text branch activations (post p1)
__device__ float g_vg[B * C];    // vg = Wv @ GvT
__device__ float g_wqk[B * C];   // wqk = kg @ Wq
__device__ float g_qb[B];        // qb = bq . kg

__device__ __forceinline__ float ex2f(float x) {
    float y;
    asm("ex2.approx.ftz.f32 %0, %1;" : "=f"(y) : "f"(x));
    return y;
}

__device__ __forceinline__ float warp_sum(float v) {
    #pragma unroll
    for (int o = 16; o; o >>= 1) v += __shfl_xor_sync(0xffffffffu, v, o);
    return v;
}

// ---------------------------------------------------------------------------
// P1: t = text @ Wg1 + bg1.  4096 outputs, one warp each. grid 512 x 256.
// ---------------------------------------------------------------------------
__global__ __launch_bounds__(256)
void p1_kernel(const float* __restrict__ text,
               const float* __restrict__ Wg1, const float* __restrict__ bg1)
{
    const int warp = (blockIdx.x * 256 + threadIdx.x) >> 5;  // 0..4095
    const int lane = threadIdx.x & 31;
    const int b = warp >> 9;
    const int j = warp & 511;
    const float* tx = text + b * C;
    float acc = 0.0f;
    #pragma unroll
    for (int t = 0; t < 8; t++) {
        const int c = lane + 32 * t;
        acc = fmaf(tx[c], Wg1[c * C2 + j], acc);
    }
    acc = warp_sum(acc);
    if (lane == 0) g_t[b * C2 + j] = acc + bg1[j];
}

// ---------------------------------------------------------------------------
// Fused prep: LN + GELU + (GvT = t@Wg2+bg2) + (vg = Wv@GvT, kg = Wk@GvT)
//             + (wqk = kg@Wq, qb = bq.kg).  One block per batch, 512 threads.
// All weight loads are LDG.128; per-SM bound ~832KB / 128B/cyc ~= 6.5K cyc.
// ---------------------------------------------------------------------------
__global__ __launch_bounds__(512)
void prep_kernel(const float* __restrict__ ln_g, const float* __restrict__ ln_b,
                 const float* __restrict__ Wg2,  const float* __restrict__ bg2,
                 const float* __restrict__ Wq,   const float* __restrict__ bq,
                 const float* __restrict__ Wk,   const float* __restrict__ Wv)
{
    const int b = blockIdx.x;
    const int tid = threadIdx.x;                 // 512 threads, 16 warps
    const int lane = tid & 31, wid = tid >> 5;

    __shared__ float t_s[C2];
    __shared__ float gv_s[C];
    __shared__ float part_f[2048];               // 8 k-chunks x 256 c (float view)
    __shared__ float kg_s[DK];
    __shared__ float red[16];
    __shared__ float bcast[2];

    // ---- LayerNorm + exact GELU over t[b, :] ----
    const float v = g_t[b * C2 + tid];
    float s1 = warp_sum(v);
    if (lane == 0) red[wid] = s1;
    __syncthreads();
    if (wid == 0) {
        float r = (lane < 16) ? red[lane] : 0.0f;
        r = warp_sum(r);
        if (lane == 0) bcast[0] = r * (1.0f / C2);
    }
    __syncthreads();
    const float mu = bcast[0];
    const float d = v - mu;
    float s2 = warp_sum(d * d);
    if (lane == 0) red[wid] = s2;
    __syncthreads();
    if (wid == 0) {
        float r = (lane < 16) ? red[lane] : 0.0f;
        r = warp_sum(r);
        if (lane == 0) bcast[1] = rsqrtf(r * (1.0f / C2) + 1e-5f);
    }
    __syncthreads();
    {
        float x = d * bcast[1] * ln_g[tid] + ln_b[tid];
        t_s[tid] = 0.5f * x * (1.0f + erff(x * 0.7071067811865476f));
    }
    __syncthreads();

    // ---- GvT[c] = sum_k t[k] * Wg2[k*C + c] + bg2[c]  (float4 over c) ----
    {
        const int q = tid & 63;       // c-group: c = 4q .. 4q+3
        const int h = tid >> 6;       // k-chunk: k in [h*64, h*64+64)
        const float4* W4 = (const float4*)Wg2;   // [512][64] float4
        float4 acc = make_float4(0.f, 0.f, 0.f, 0.f);
        #pragma unroll 16
        for (int kk = 0; kk < 64; kk++) {
            const int k = h * 64 + kk;
            const float tk = t_s[k];
            const float4 w = W4[k * 64 + q];
            acc.x = fmaf(tk, w.x, acc.x);
            acc.y = fmaf(tk, w.y, acc.y);
            acc.z = fmaf(tk, w.z, acc.z);
            acc.w = fmaf(tk, w.w, acc.w);
        }
        // part layout: part_f[h*256 + c]
        part_f[h * 256 + 4 * q + 0] = acc.x;
        part_f[h * 256 + 4 * q + 1] = acc.y;
        part_f[h * 256 + 4 * q + 2] = acc.z;
        part_f[h * 256 + 4 * q + 3] = acc.w;
    }
    __syncthreads();
    if (tid < C) {
        float g = bg2[tid];
        #pragma unroll
        for (int h = 0; h < 8; h++) g += part_f[h * 256 + tid];
        gv_s[tid] = g;
    }
    __syncthreads();

    // ---- vg[c] = Wv[c,:] . gv   (warp per output, 16 outputs/warp) ----
    {
        const float4* Wv4 = (const float4*)Wv;        // [256][64] float4
        const float4* gv4 = (const float4*)gv_s;
        const float4 gA = gv4[lane];                  // k = 4*lane..
        const float4 gB = gv4[32 + lane];             // k = 128+4*lane..
        #pragma unroll
        for (int oo = 0; oo < 16; oo++) {
            const int c = wid * 16 + oo;
            const float4 wA = Wv4[c * 64 + lane];
            const float4 wB = Wv4[c * 64 + 32 + lane];
            float p = wA.x * gA.x + wA.y * gA.y + wA.z * gA.z + wA.w * gA.w
                    + wB.x * gB.x + wB.y * gB.y + wB.z * gB.z + wB.w * gB.w;
            p = warp_sum(p);
            if (lane == 0) g_vg[b * C + c] = p;
        }
        // ---- kg[d] = Wk[d,:] . gv   (2 outputs/warp) ----
        const float4* Wk4 = (const float4*)Wk;        // [32][64] float4
        #pragma unroll
        for (int oo = 0; oo < 2; oo++) {
            const int dd = wid * 2 + oo;
            const float4 wA = Wk4[dd * 64 + lane];
            const float4 wB = Wk4[dd * 64 + 32 + lane];
            float p = wA.x * gA.x + wA.y * gA.y + wA.z * gA.z + wA.w * gA.w
                    + wB.x * gB.x + wB.y * gB.y + wB.z * gB.z + wB.w * gB.w;
            p = warp_sum(p);
            if (lane == 0) kg_s[dd] = p;
        }
    }
    __syncthreads();

    // ---- wqk[c] = sum_d kg[d] * Wq[d*C + c];  qb = bq . kg ----
    if (tid < C) {
        float acc = 0.0f;
        #pragma unroll
        for (int dd = 0; dd < DK; dd++) acc = fmaf(kg_s[dd], Wq[dd * C + tid], acc);
        g_wqk[b * C + tid] = acc;
    }
    if (wid == 0) {
        float p = bq[lane] * kg_s[lane];
        p = warp_sum(p);
        if (lane == 0) g_qb[b] = p;
    }
}

// ---------------------------------------------------------------------------
// Attention: block = 256 threads, 64 pixels, 4 threads per pixel.
// Thread s owns contiguous channels c in [64s, 64s+64): img column cached in
// registers across dot -> exp-loop -> epilogue (img read ONCE). grid (36, 8).
// ---------------------------------------------------------------------------
__global__ __launch_bounds__(256, 2)
void attn_kernel(const float* __restrict__ img,
                 const float* __restrict__ l,
                 const float* __restrict__ bv,
                 const float* __restrict__ gamma_p,
                 float* __restrict__ out)
{
    const int b = blockIdx.y;
    const int tid = threadIdx.x;
    const int s = tid >> 6;      // 0..3  split index
    const int p = tid & 63;      // pixel within block
    const int i = blockIdx.x * 64 + p;
    const int lane = tid & 31, wid = tid >> 5;
    const int c0 = s * 64;

    __shared__ float ls[HW];
    __shared__ float wq[C];
    __shared__ float vgs[C];
    __shared__ float bvs[C];
    __shared__ float partA[256];
    __shared__ float partS[256];
    __shared__ float partT[256];
    __shared__ float rmx[8], rmn[8];

    const float gm = *gamma_p;
    const float qb = g_qb[b];

    // load l (+min/max), coefficient vectors
    float mx = -1e30f, mn = 1e30f;
    #pragma unroll
    for (int j = tid; j < HW; j += 256) {
        const float v = l[j];
        ls[j] = v;
        mx = fmaxf(mx, v);
        mn = fminf(mn, v);
    }
    wq[tid]  = g_wqk[b * C + tid];
    vgs[tid] = g_vg[b * C + tid];
    bvs[tid] = bv[tid];

    #pragma unroll
    for (int o = 16; o; o >>= 1) {
        mx = fmaxf(mx, __shfl_xor_sync(0xffffffffu, mx, o));
        mn = fminf(mn, __shfl_xor_sync(0xffffffffu, mn, o));
    }
    if (lane == 0) { rmx[wid] = mx; rmn[wid] = mn; }
    __syncthreads();
    float lmax = rmx[0], lmin = rmn[0];
    #pragma unroll
    for (int k = 1; k < 8; k++) {
        lmax = fmaxf(lmax, rmx[k]);
        lmin = fminf(lmin, rmn[k]);
    }

    // load img chunk (64 contiguous channels) into registers; partial dot
    float im[64];
    const float* xb = img + (size_t)b * C * HW + (size_t)c0 * HW + i;
    float a = 0.0f;
    #pragma unroll
    for (int cc = 0; cc < 64; cc++) {
        im[cc] = xb[(size_t)cc * HW];
        a = fmaf(wq[c0 + cc], im[cc], a);
    }
    partA[tid] = a;
    __syncthreads();
    const float af = qb + partA[p] + partA[64 + p] + partA[128 + p] + partA[192 + p];

    // softmax-weighted sum of l (rank-1 logits), exp2 domain, contiguous j chunk
    const float al = af * 1.4426950408889634f;
    const float m2 = (al > 0.0f) ? al * lmax : al * lmin;
    float S = 0.0f, T = 0.0f;
    const int j0 = s * (HW / 4);
    #pragma unroll 8
    for (int jj = 0; jj < HW / 4; jj++) {
        const float lj = ls[j0 + jj];
        const float e = ex2f(fmaf(al, lj, -m2));
        S += e;
        T = fmaf(lj, e, T);
    }
    partS[tid] = S;
    partT[tid] = T;
    __syncthreads();
    const float Ss = partS[p] + partS[64 + p] + partS[128 + p] + partS[192 + p];
    const float Ts = partT[p] + partT[64 + p] + partT[128 + p] + partT[192 + p];
    const float sv = Ts / Ss;

    // out[b,c,i] = img + gamma * (vg[c]*sv + bv[c]) using register-cached img
    float* ob = out + (size_t)b * C * HW + (size_t)c0 * HW + i;
    #pragma unroll
    for (int cc = 0; cc < 64; cc++) {
        ob[(size_t)cc * HW] = fmaf(gm, fmaf(vgs[c0 + cc], sv, bvs[c0 + cc]), im[cc]);
    }
}

extern "C" void kernel_launch(void* const* d_in, const int* in_sizes, int n_in,
                              void* d_out, int out_size)
{
    const float* img   = (const float*)d_in[0];
    const float* text  = (const float*)d_in[1];
    const float* l     = (const float*)d_in[2];
    const float* Wg1   = (const float*)d_in[3];
    const float* bg1   = (const float*)d_in[4];
    const float* ln_g  = (const float*)d_in[5];
    const float* ln_b  = (const float*)d_in[6];
    const float* Wg2   = (const float*)d_in[7];
    const float* bg2   = (const float*)d_in[8];
    const float* Wq    = (const float*)d_in[9];
    const float* bq    = (const float*)d_in[10];
    const float* Wk    = (const float*)d_in[11];
    // d_in[12] = bk : cancels in softmax, unused
    const float* Wv    = (const float*)d_in[13];
    const float* bv    = (const float*)d_in[14];
    const float* gamma = (const float*)d_in[15];
    float* out = (float*)d_out;

    p1_kernel<<<512, 256>>>(text, Wg1, bg1);
    prep_kernel<<<B, 512>>>(ln_g, ln_b, Wg2, bg2, Wq, bq, Wk, Wv);
    dim3 grid(HW / 64, B);
    attn_kernel<<<grid, 256>>>(img, l, bv, gamma, out);
}

// round 5
// speedup vs baseline: 3.4559x; 1.1034x over previous
#include <cuda_runtime.h>
#include <cuda_bf16.h>

#define B 8
#define C 256
#define HW 2304
#define DK 32
#define C2 512

// Scratch (device globals — no allocation allowed)
__device__ float g_t[B * C2];    // text branch activations (post p1)
__device__ float g_vg[B * C];    // vg = Wv @ GvT
__device__ float g_wqk[B * C];   // wqk = kg @ Wq
__device__ float g_qb[B];        // qb = bq . kg
__device__ float g_lmax, g_lmin; // reduced once from l

__device__ __forceinline__ float ex2f(float x) {
    float y;
    asm("ex2.approx.ftz.f32 %0, %1;" : "=f"(y) : "f"(x));
    return y;
}

__device__ __forceinline__ float warp_sum(float v) {
    #pragma unroll
    for (int o = 16; o; o >>= 1) v += __shfl_xor_sync(0xffffffffu, v, o);
    return v;
}

// ---------------------------------------------------------------------------
// P1: t = text @ Wg1 + bg1 with COALESCED Wg1 reads (lanes vary over j).
// grid 65 x 256: blocks 0..63 = (b, j-tile of 64) x 4-way c-split;
// block 64 reduces l -> g_lmax/g_lmin.
// ---------------------------------------------------------------------------
__global__ __launch_bounds__(256)
void p1_kernel(const float* __restrict__ text,
               const float* __restrict__ Wg1, const float* __restrict__ bg1,
               const float* __restrict__ l)
{
    const int tid = threadIdx.x;

    if (blockIdx.x == 64) {
        // reduce l min/max
        __shared__ float rmx[8], rmn[8];
        float mx = -1e30f, mn = 1e30f;
        #pragma unroll
        for (int j = tid; j < HW; j += 256) {
            const float v = l[j];
            mx = fmaxf(mx, v);
            mn = fminf(mn, v);
        }
        #pragma unroll
        for (int o = 16; o; o >>= 1) {
            mx = fmaxf(mx, __shfl_xor_sync(0xffffffffu, mx, o));
            mn = fminf(mn, __shfl_xor_sync(0xffffffffu, mn, o));
        }
        if ((tid & 31) == 0) { rmx[tid >> 5] = mx; rmn[tid >> 5] = mn; }
        __syncthreads();
        if (tid == 0) {
            float a = rmx[0], b2 = rmn[0];
            #pragma unroll
            for (int k = 1; k < 8; k++) { a = fmaxf(a, rmx[k]); b2 = fminf(b2, rmn[k]); }
            g_lmax = a; g_lmin = b2;
        }
        return;
    }

    const int b  = blockIdx.x >> 3;        // batch
    const int j0 = (blockIdx.x & 7) * 64;  // j tile
    const int jl = tid & 63;               // j within tile (lanes consecutive)
    const int cg = tid >> 6;               // c-group 0..3

    __shared__ float text_s[C];
    __shared__ float part[256];

    if (tid < C) text_s[tid] = text[b * C + tid];
    __syncthreads();

    float acc = 0.0f;
    #pragma unroll 16
    for (int cc = 0; cc < 64; cc++) {
        const int c = cg * 64 + cc;
        acc = fmaf(text_s[c], Wg1[c * C2 + j0 + jl], acc);
    }
    part[tid] = acc;
    __syncthreads();
    if (tid < 64) {
        const float s = part[tid] + part[64 + tid] + part[128 + tid] + part[192 + tid];
        g_t[b * C2 + j0 + tid] = s + bg1[j0 + tid];
    }
}

// ---------------------------------------------------------------------------
// Fused prep: LN + GELU + (GvT = t@Wg2+bg2) + (vg = Wv@GvT, kg = Wk@GvT)
//             + (wqk = kg@Wq, qb = bq.kg).  One block per batch, 512 threads.
// ---------------------------------------------------------------------------
__global__ __launch_bounds__(512)
void prep_kernel(const float* __restrict__ ln_g, const float* __restrict__ ln_b,
                 const float* __restrict__ Wg2,  const float* __restrict__ bg2,
                 const float* __restrict__ Wq,   const float* __restrict__ bq,
                 const float* __restrict__ Wk,   const float* __restrict__ Wv)
{
    const int b = blockIdx.x;
    const int tid = threadIdx.x;                 // 512 threads, 16 warps
    const int lane = tid & 31, wid = tid >> 5;

    __shared__ float t_s[C2];
    __shared__ float gv_s[C];
    __shared__ float part_f[2048];               // 8 k-chunks x 256 c
    __shared__ float kg_s[DK];
    __shared__ float red[16];
    __shared__ float bcast[2];

    // ---- LayerNorm + exact GELU over t[b, :] ----
    const float v = g_t[b * C2 + tid];
    float s1 = warp_sum(v);
    if (lane == 0) red[wid] = s1;
    __syncthreads();
    if (wid == 0) {
        float r = (lane < 16) ? red[lane] : 0.0f;
        r = warp_sum(r);
        if (lane == 0) bcast[0] = r * (1.0f / C2);
    }
    __syncthreads();
    const float mu = bcast[0];
    const float d = v - mu;
    float s2 = warp_sum(d * d);
    if (lane == 0) red[wid] = s2;
    __syncthreads();
    if (wid == 0) {
        float r = (lane < 16) ? red[lane] : 0.0f;
        r = warp_sum(r);
        if (lane == 0) bcast[1] = rsqrtf(r * (1.0f / C2) + 1e-5f);
    }
    __syncthreads();
    {
        float x = d * bcast[1] * ln_g[tid] + ln_b[tid];
        t_s[tid] = 0.5f * x * (1.0f + erff(x * 0.7071067811865476f));
    }
    __syncthreads();

    // ---- GvT[c] = sum_k t[k] * Wg2[k*C + c] + bg2[c]  (float4 over c) ----
    {
        const int q = tid & 63;       // c-group: c = 4q .. 4q+3
        const int h = tid >> 6;       // k-chunk: k in [h*64, h*64+64)
        const float4* W4 = (const float4*)Wg2;   // [512][64] float4
        float4 acc = make_float4(0.f, 0.f, 0.f, 0.f);
        #pragma unroll 16
        for (int kk = 0; kk < 64; kk++) {
            const int k = h * 64 + kk;
            const float tk = t_s[k];
            const float4 w = W4[k * 64 + q];
            acc.x = fmaf(tk, w.x, acc.x);
            acc.y = fmaf(tk, w.y, acc.y);
            acc.z = fmaf(tk, w.z, acc.z);
            acc.w = fmaf(tk, w.w, acc.w);
        }
        part_f[h * 256 + 4 * q + 0] = acc.x;
        part_f[h * 256 + 4 * q + 1] = acc.y;
        part_f[h * 256 + 4 * q + 2] = acc.z;
        part_f[h * 256 + 4 * q + 3] = acc.w;
    }
    __syncthreads();
    if (tid < C) {
        float g = bg2[tid];
        #pragma unroll
        for (int h = 0; h < 8; h++) g += part_f[h * 256 + tid];
        gv_s[tid] = g;
    }
    __syncthreads();

    // ---- vg[c] = Wv[c,:] . gv   (warp per output, 16 outputs/warp) ----
    {
        const float4* Wv4 = (const float4*)Wv;        // [256][64] float4
        const float4* gv4 = (const float4*)gv_s;
        const float4 gA = gv4[lane];
        const float4 gB = gv4[32 + lane];
        #pragma unroll
        for (int oo = 0; oo < 16; oo++) {
            const int c = wid * 16 + oo;
            const float4 wA = Wv4[c * 64 + lane];
            const float4 wB = Wv4[c * 64 + 32 + lane];
            float p = wA.x * gA.x + wA.y * gA.y + wA.z * gA.z + wA.w * gA.w
                    + wB.x * gB.x + wB.y * gB.y + wB.z * gB.z + wB.w * gB.w;
            p = warp_sum(p);
            if (lane == 0) g_vg[b * C + c] = p;
        }
        // ---- kg[d] = Wk[d,:] . gv   (2 outputs/warp) ----
        const float4* Wk4 = (const float4*)Wk;        // [32][64] float4
        #pragma unroll
        for (int oo = 0; oo < 2; oo++) {
            const int dd = wid * 2 + oo;
            const float4 wA = Wk4[dd * 64 + lane];
            const float4 wB = Wk4[dd * 64 + 32 + lane];
            float p = wA.x * gA.x + wA.y * gA.y + wA.z * gA.z + wA.w * gA.w
                    + wB.x * gB.x + wB.y * gB.y + wB.z * gB.z + wB.w * gB.w;
            p = warp_sum(p);
            if (lane == 0) kg_s[dd] = p;
        }
    }
    __syncthreads();

    // ---- wqk[c] = sum_d kg[d] * Wq[d*C + c];  qb = bq . kg ----
    if (tid < C) {
        float acc = 0.0f;
        #pragma unroll
        for (int dd = 0; dd < DK; dd++) acc = fmaf(kg_s[dd], Wq[dd * C + tid], acc);
        g_wqk[b * C + tid] = acc;
    }
    if (wid == 0) {
        float p = bq[lane] * kg_s[lane];
        p = warp_sum(p);
        if (lane == 0) g_qb[b] = p;
    }
}

// ---------------------------------------------------------------------------
// Attention: block = 256 threads, 64 pixels, 4 threads per pixel.
// Thread s owns contiguous channels c in [64s, 64s+64): img column cached in
// registers (read ONCE). img LDGs front-batched before smem fills so DRAM
// latency overlaps. lmax/lmin precomputed. grid (36, 8).
// ---------------------------------------------------------------------------
__global__ __launch_bounds__(256, 2)
void attn_kernel(const float* __restrict__ img,
                 const float* __restrict__ l,
                 const float* __restrict__ bv,
                 const float* __restrict__ gamma_p,
                 float* __restrict__ out)
{
    const int b = blockIdx.y;
    const int tid = threadIdx.x;
    const int s = tid >> 6;      // 0..3  split index
    const int p = tid & 63;      // pixel within block
    const int i = blockIdx.x * 64 + p;
    const int c0 = s * 64;

    __shared__ float ls[HW];
    __shared__ float wq[C];
    __shared__ float vgs[C];
    __shared__ float bvs[C];
    __shared__ float partA[256];
    __shared__ float partS[256];
    __shared__ float partT[256];

    // front-batch img loads (64 contiguous channels per thread) into registers
    float im[64];
    const float* xb = img + (size_t)b * C * HW + (size_t)c0 * HW + i;
    #pragma unroll
    for (int cc = 0; cc < 64; cc++) im[cc] = xb[(size_t)cc * HW];

    const float gm   = *gamma_p;
    const float qb   = g_qb[b];
    const float lmax = g_lmax;
    const float lmin = g_lmin;

    // smem fills overlap the in-flight img loads
    #pragma unroll
    for (int j = tid; j < HW; j += 256) ls[j] = l[j];
    wq[tid]  = g_wqk[b * C + tid];
    vgs[tid] = g_vg[b * C + tid];
    bvs[tid] = bv[tid];
    __syncthreads();

    // partial dot: a_s = sum_{c in chunk} wq[c] * img[c,i]
    float a = 0.0f;
    #pragma unroll
    for (int cc = 0; cc < 64; cc++) a = fmaf(wq[c0 + cc], im[cc], a);
    partA[tid] = a;
    __syncthreads();
    const float af = qb + partA[p] + partA[64 + p] + partA[128 + p] + partA[192 + p];

    // softmax-weighted sum of l (rank-1 logits), exp2 domain, contiguous j chunk
    const float al = af * 1.4426950408889634f;
    const float m2 = (al > 0.0f) ? al * lmax : al * lmin;
    float S = 0.0f, T = 0.0f;
    const int j0 = s * (HW / 4);
    #pragma unroll 8
    for (int jj = 0; jj < HW / 4; jj++) {
        const float lj = ls[j0 + jj];
        const float e = ex2f(fmaf(al, lj, -m2));
        S += e;
        T = fmaf(lj, e, T);
    }
    partS[tid] = S;
    partT[tid] = T;
    __syncthreads();
    const float Ss = partS[p] + partS[64 + p] + partS[128 + p] + partS[192 + p];
    const float Ts = partT[p] + partT[64 + p] + partT[128 + p] + partT[192 + p];
    const float sv = Ts / Ss;

    // out[b,c,i] = img + gamma * (vg[c]*sv + bv[c]) using register-cached img
    float* ob = out + (size_t)b * C * HW + (size_t)c0 * HW + i;
    #pragma unroll
    for (int cc = 0; cc < 64; cc++) {
        ob[(size_t)cc * HW] = fmaf(gm, fmaf(vgs[c0 + cc], sv, bvs[c0 + cc]), im[cc]);
    }
}

extern "C" void kernel_launch(void* const* d_in, const int* in_sizes, int n_in,
                              void* d_out, int out_size)
{
    const float* img   = (const float*)d_in[0];
    const float* text  = (const float*)d_in[1];
    const float* l     = (const float*)d_in[2];
    const float* Wg1   = (const float*)d_in[3];
    const float* bg1   = (const float*)d_in[4];
    const float* ln_g  = (const float*)d_in[5];
    const float* ln_b  = (const float*)d_in[6];
    const float* Wg2   = (const float*)d_in[7];
    const float* bg2   = (const float*)d_in[8];
    const float* Wq    = (const float*)d_in[9];
    const float* bq    = (const float*)d_in[10];
    const float* Wk    = (const float*)d_in[11];
    // d_in[12] = bk : cancels in softmax, unused
    const float* Wv    = (const float*)d_in[13];
    const float* bv    = (const float*)d_in[14];
    const float* gamma = (const float*)d_in[15];
    float* out = (float*)d_out;

    p1_kernel<<<65, 256>>>(text, Wg1, bg1, l);
    prep_kernel<<<B, 512>>>(ln_g, ln_b, Wg2, bg2, Wq, bq, Wk, Wv);
    dim3 grid(HW / 64, B);
    attn_kernel<<<grid, 256>>>(img, l, bv, gamma, out);
}

// round 6
// speedup vs baseline: 3.5234x; 1.0195x over previous
#include <cuda_runtime.h>
#include <cuda_bf16.h>

#define B 8
#define C 256
#define HW 2304
#define DK 32
#define C2 512

// Scratch (device globals — no allocation allowed)
__device__ float g_tp[8 * B * C2]; // p1 partials: [ct][b][j]
__device__ float g_vg[B * C];      // vg = Wv @ GvT
__device__ float g_wqk[B * C];     // wqk = kg @ Wq
__device__ float g_qb[B];          // qb = bq . kg
__device__ float g_lmax, g_lmin;   // reduced once from l

__device__ __forceinline__ float ex2f(float x) {
    float y;
    asm("ex2.approx.ftz.f32 %0, %1;" : "=f"(y) : "f"(x));
    return y;
}

__device__ __forceinline__ float warp_sum(float v) {
    #pragma unroll
    for (int o = 16; o; o >>= 1) v += __shfl_xor_sync(0xffffffffu, v, o);
    return v;
}

// ---------------------------------------------------------------------------
// P1: partial t = text @ Wg1 over a 32-channel tile. grid 129 x 256.
// blocks 0..127: b(8) x jhalf(2, 256 j) x ctile(8, 32 c); block 128: l min/max.
// Each thread: 32 coalesced LDGs (lanes vary over j) -> one partial per j.
// ---------------------------------------------------------------------------
__global__ __launch_bounds__(256)
void p1_kernel(const float* __restrict__ text,
               const float* __restrict__ Wg1,
               const float* __restrict__ l)
{
    const int tid = threadIdx.x;
    const int blk = blockIdx.x;

    if (blk == 128) {
        __shared__ float rmx[8], rmn[8];
        float mx = -1e30f, mn = 1e30f;
        #pragma unroll
        for (int j = tid; j < HW; j += 256) {
            const float v = l[j];
            mx = fmaxf(mx, v);
            mn = fminf(mn, v);
        }
        #pragma unroll
        for (int o = 16; o; o >>= 1) {
            mx = fmaxf(mx, __shfl_xor_sync(0xffffffffu, mx, o));
            mn = fminf(mn, __shfl_xor_sync(0xffffffffu, mn, o));
        }
        if ((tid & 31) == 0) { rmx[tid >> 5] = mx; rmn[tid >> 5] = mn; }
        __syncthreads();
        if (tid == 0) {
            float a = rmx[0], b2 = rmn[0];
            #pragma unroll
            for (int k = 1; k < 8; k++) { a = fmaxf(a, rmx[k]); b2 = fminf(b2, rmn[k]); }
            g_lmax = a; g_lmin = b2;
        }
        return;
    }

    const int b  = blk >> 4;
    const int jh = (blk >> 3) & 1;
    const int ct = blk & 7;
    const int j  = jh * 256 + tid;

    __shared__ float text_s[32];
    if (tid < 32) text_s[tid] = text[b * C + ct * 32 + tid];
    __syncthreads();

    float acc = 0.0f;
    #pragma unroll
    for (int cc = 0; cc < 32; cc++) {
        acc = fmaf(text_s[cc], Wg1[(ct * 32 + cc) * C2 + j], acc);
    }
    g_tp[ct * (B * C2) + b * C2 + j] = acc;
}

// ---------------------------------------------------------------------------
// Fused prep: combine p1 partials + bias, LN + GELU, GvT = t@Wg2+bg2,
// vg = Wv@GvT, kg = Wk@GvT, wqk = kg@Wq, qb = bq.kg.
// One block per batch, 512 threads.
// ---------------------------------------------------------------------------
__global__ __launch_bounds__(512)
void prep_kernel(const float* __restrict__ bg1,
                 const float* __restrict__ ln_g, const float* __restrict__ ln_b,
                 const float* __restrict__ Wg2,  const float* __restrict__ bg2,
                 const float* __restrict__ Wq,   const float* __restrict__ bq,
                 const float* __restrict__ Wk,   const float* __restrict__ Wv)
{
    const int b = blockIdx.x;
    const int tid = threadIdx.x;                 // 512 threads, 16 warps
    const int lane = tid & 31, wid = tid >> 5;

    __shared__ float t_s[C2];
    __shared__ float gv_s[C];
    __shared__ float part_f[2048];               // 8 k-chunks x 256 c
    __shared__ float kg_s[DK];
    __shared__ float red[16];
    __shared__ float bcast[2];

    // ---- combine p1 partials (fixed order: deterministic) ----
    float v = bg1[tid];
    #pragma unroll
    for (int ct = 0; ct < 8; ct++) v += g_tp[ct * (B * C2) + b * C2 + tid];

    // ---- LayerNorm + exact GELU ----
    float s1 = warp_sum(v);
    if (lane == 0) red[wid] = s1;
    __syncthreads();
    if (wid == 0) {
        float r = (lane < 16) ? red[lane] : 0.0f;
        r = warp_sum(r);
        if (lane == 0) bcast[0] = r * (1.0f / C2);
    }
    __syncthreads();
    const float mu = bcast[0];
    const float d = v - mu;
    float s2 = warp_sum(d * d);
    if (lane == 0) red[wid] = s2;
    __syncthreads();
    if (wid == 0) {
        float r = (lane < 16) ? red[lane] : 0.0f;
        r = warp_sum(r);
        if (lane == 0) bcast[1] = rsqrtf(r * (1.0f / C2) + 1e-5f);
    }
    __syncthreads();
    {
        float x = d * bcast[1] * ln_g[tid] + ln_b[tid];
        t_s[tid] = 0.5f * x * (1.0f + erff(x * 0.7071067811865476f));
    }
    __syncthreads();

    // ---- GvT[c] = sum_k t[k] * Wg2[k*C + c] + bg2[c]  (float4 over c) ----
    {
        const int q = tid & 63;       // c-group: c = 4q .. 4q+3
        const int h = tid >> 6;       // k-chunk: k in [h*64, h*64+64)
        const float4* W4 = (const float4*)Wg2;   // [512][64] float4
        float4 acc = make_float4(0.f, 0.f, 0.f, 0.f);
        #pragma unroll 16
        for (int kk = 0; kk < 64; kk++) {
            const int k = h * 64 + kk;
            const float tk = t_s[k];
            const float4 w = W4[k * 64 + q];
            acc.x = fmaf(tk, w.x, acc.x);
            acc.y = fmaf(tk, w.y, acc.y);
            acc.z = fmaf(tk, w.z, acc.z);
            acc.w = fmaf(tk, w.w, acc.w);
        }
        part_f[h * 256 + 4 * q + 0] = acc.x;
        part_f[h * 256 + 4 * q + 1] = acc.y;
        part_f[h * 256 + 4 * q + 2] = acc.z;
        part_f[h * 256 + 4 * q + 3] = acc.w;
    }
    __syncthreads();
    if (tid < C) {
        float g = bg2[tid];
        #pragma unroll
        for (int h = 0; h < 8; h++) g += part_f[h * 256 + tid];
        gv_s[tid] = g;
    }
    __syncthreads();

    // ---- vg[c] = Wv[c,:] . gv   (warp per output, 16 outputs/warp) ----
    {
        const float4* Wv4 = (const float4*)Wv;        // [256][64] float4
        const float4* gv4 = (const float4*)gv_s;
        const float4 gA = gv4[lane];
        const float4 gB = gv4[32 + lane];
        #pragma unroll
        for (int oo = 0; oo < 16; oo++) {
            const int c = wid * 16 + oo;
            const float4 wA = Wv4[c * 64 + lane];
            const float4 wB = Wv4[c * 64 + 32 + lane];
            float p = wA.x * gA.x + wA.y * gA.y + wA.z * gA.z + wA.w * gA.w
                    + wB.x * gB.x + wB.y * gB.y + wB.z * gB.z + wB.w * gB.w;
            p = warp_sum(p);
            if (lane == 0) g_vg[b * C + c] = p;
        }
        // ---- kg[d] = Wk[d,:] . gv   (2 outputs/warp) ----
        const float4* Wk4 = (const float4*)Wk;        // [32][64] float4
        #pragma unroll
        for (int oo = 0; oo < 2; oo++) {
            const int dd = wid * 2 + oo;
            const float4 wA = Wk4[dd * 64 + lane];
            const float4 wB = Wk4[dd * 64 + 32 + lane];
            float p = wA.x * gA.x + wA.y * gA.y + wA.z * gA.z + wA.w * gA.w
                    + wB.x * gB.x + wB.y * gB.y + wB.z * gB.z + wB.w * gB.w;
            p = warp_sum(p);
            if (lane == 0) kg_s[dd] = p;
        }
    }
    __syncthreads();

    // ---- wqk[c] = sum_d kg[d] * Wq[d*C + c];  qb = bq . kg ----
    if (tid < C) {
        float acc = 0.0f;
        #pragma unroll
        for (int dd = 0; dd < DK; dd++) acc = fmaf(kg_s[dd], Wq[dd * C + tid], acc);
        g_wqk[b * C + tid] = acc;
    }
    if (wid == 0) {
        float p = bq[lane] * kg_s[lane];
        p = warp_sum(p);
        if (lane == 0) g_qb[b] = p;
    }
}

// ---------------------------------------------------------------------------
// Attention: block = 256 threads = 8 warps; warp s handles split s for the
// block's 32 pixels (lane = pixel). Thread owns contiguous channels
// c in [32s, 32s+32), img cached in registers (read ONCE). grid (72, 8).
// ---------------------------------------------------------------------------
__global__ __launch_bounds__(256, 3)
void attn_kernel(const float* __restrict__ img,
                 const float* __restrict__ l,
                 const float* __restrict__ bv,
                 const float* __restrict__ gamma_p,
                 float* __restrict__ out)
{
    const int b = blockIdx.y;
    const int tid = threadIdx.x;
    const int p = tid & 31;      // pixel within block (lane)
    const int s = tid >> 5;      // split 0..7 (warp)
    const int i = blockIdx.x * 32 + p;
    const int c0 = s * 32;

    __shared__ float ls[HW];
    __shared__ float wq[C];
    __shared__ float vgs[C];
    __shared__ float bvs[C];
    __shared__ float partA[256];
    __shared__ float partS[256];
    __shared__ float partT[256];

    // front-batch img loads (32 contiguous channels per thread) into registers
    float im[32];
    const float* xb = img + (size_t)b * C * HW + (size_t)c0 * HW + i;
    #pragma unroll
    for (int cc = 0; cc < 32; cc++) im[cc] = xb[(size_t)cc * HW];

    const float gm   = *gamma_p;
    const float qb   = g_qb[b];
    const float lmax = g_lmax;
    const float lmin = g_lmin;

    // smem fills overlap the in-flight img loads
    #pragma unroll
    for (int j = tid; j < HW; j += 256) ls[j] = l[j];
    wq[tid]  = g_wqk[b * C + tid];
    vgs[tid] = g_vg[b * C + tid];
    bvs[tid] = bv[tid];
    __syncthreads();

    // partial dot over this thread's 32 channels
    float a = 0.0f;
    #pragma unroll
    for (int cc = 0; cc < 32; cc++) a = fmaf(wq[c0 + cc], im[cc], a);
    partA[tid] = a;
    __syncthreads();
    float af = qb;
    #pragma unroll
    for (int k = 0; k < 8; k++) af += partA[k * 32 + p];

    // softmax-weighted sum of l (rank-1 logits), exp2 domain, contiguous j chunk
    const float al = af * 1.4426950408889634f;
    const float m2 = (al > 0.0f) ? al * lmax : al * lmin;
    float S = 0.0f, T = 0.0f;
    const int j0 = s * (HW / 8);
    #pragma unroll 8
    for (int jj = 0; jj < HW / 8; jj++) {
        const float lj = ls[j0 + jj];
        const float e = ex2f(fmaf(al, lj, -m2));
        S += e;
        T = fmaf(lj, e, T);
    }
    partS[tid] = S;
    partT[tid] = T;
    __syncthreads();
    float Ss = 0.0f, Ts = 0.0f;
    #pragma unroll
    for (int k = 0; k < 8; k++) {
        Ss += partS[k * 32 + p];
        Ts += partT[k * 32 + p];
    }
    const float sv = Ts / Ss;

    // out[b,c,i] = img + gamma * (vg[c]*sv + bv[c]) using register-cached img
    float* ob = out + (size_t)b * C * HW + (size_t)c0 * HW + i;
    #pragma unroll
    for (int cc = 0; cc < 32; cc++) {
        ob[(size_t)cc * HW] = fmaf(gm, fmaf(vgs[c0 + cc], sv, bvs[c0 + cc]), im[cc]);
    }
}

extern "C" void kernel_launch(void* const* d_in, const int* in_sizes, int n_in,
                              void* d_out, int out_size)
{
    const float* img   = (const float*)d_in[0];
    const float* text  = (const float*)d_in[1];
    const float* l     = (const float*)d_in[2];
    const float* Wg1   = (const float*)d_in[3];
    const float* bg1   = (const float*)d_in[4];
    const float* ln_g  = (const float*)d_in[5];
    const float* ln_b  = (const float*)d_in[6];
    const float* Wg2   = (const float*)d_in[7];
    const float* bg2   = (const float*)d_in[8];
    const float* Wq    = (const float*)d_in[9];
    const float* bq    = (const float*)d_in[10];
    const float* Wk    = (const float*)d_in[11];
    // d_in[12] = bk : cancels in softmax, unused
    const float* Wv    = (const float*)d_in[13];
    const float* bv    = (const float*)d_in[14];
    const float* gamma = (const float*)d_in[15];
    float* out = (float*)d_out;

    p1_kernel<<<129, 256>>>(text, Wg1, l);
    prep_kernel<<<B, 512>>>(bg1, ln_g, ln_b, Wg2, bg2, Wq, bq, Wk, Wv);
    dim3 grid(HW / 32, B);
    attn_kernel<<<grid, 256>>>(img, l, bv, gamma, out);
}